// round 1
// baseline (speedup 1.0000x reference)
#include <cuda_runtime.h>

// Fixed problem structure (from _build_graph: M=512, N=1024, SHIFTS=(0,7,101)):
//   E = 3072 edges, every check has degree 6, every variable degree 3.
//   edges sorted by (check, var) => check c owns edges [6c, 6c+6).
//   v_sum pairs: exactly 2 per edge, grouped in edge order (seg_vsum = e).
//   final pairs: exactly 3 per var, grouped in var order (seg_final = v).
#define ITERS 5
#define MCHK  512
#define NVAR  1024
#define NEDGE 3072

__global__ __launch_bounds__(512, 2)
void bp_decode_kernel(const float* __restrict__ llr,        // [B, N]
                      const float* __restrict__ w_iter,     // [ITERS, 2E]
                      const float* __restrict__ llr_iter,   // [ITERS, N]
                      const float* __restrict__ w_final,    // [E] (3 per var, var order)
                      const float* __restrict__ llr_final,  // [N]
                      const int*   __restrict__ vs_idx,     // [2E]
                      const int*   __restrict__ fin_idx,    // [E] (3 per var, var order)
                      const int*   __restrict__ edge_var,   // [E]
                      float*       __restrict__ out)        // [B, N]
{
    __shared__ float sm[NEDGE];

    const int b  = blockIdx.x;
    const int c  = threadIdx.x;     // check id, 0..511
    const int e0 = 6 * c;
    const float* __restrict__ llr_b = llr + (size_t)b * NVAR;

    // Constant per-thread graph data (same for every batch item -> L1/L2 hits)
    int   sib0[6], sib1[6], ev[6];
    float lv[6];
#pragma unroll
    for (int j = 0; j < 6; ++j) {
        const int e = e0 + j;
        sib0[j] = vs_idx[2 * e];
        sib1[j] = vs_idx[2 * e + 1];
        ev[j]   = edge_var[e];
        lv[j]   = __ldg(&llr_b[ev[j]]);
    }

    float c2v[6];
#pragma unroll
    for (int j = 0; j < 6; ++j) c2v[j] = 0.0f;

    for (int t = 0; t < ITERS; ++t) {
        // publish c2v messages
#pragma unroll
        for (int j = 0; j < 6; ++j) sm[e0 + j] = c2v[j];
        __syncthreads();

        const float* __restrict__ wt = w_iter  + t * (2 * NEDGE);
        const float* __restrict__ lt = llr_iter + t * NVAR;

        // variable-node update: v2c = tanh(0.5*(sum_sib c2v*w + llr*llr_iter))
        float v2c[6];
#pragma unroll
        for (int j = 0; j < 6; ++j) {
            const int e = e0 + j;
            float summed = sm[sib0[j]] * wt[2 * e] + sm[sib1[j]] * wt[2 * e + 1];
            float arg    = summed + lv[j] * lt[ev[j]];
            // tanh(arg/2) = 1 - 2/(1+exp(arg));  exp->inf gives 1, exp->0 gives -1 (NaN-safe)
            float ea = __expf(arg);
            v2c[j] = 1.0f - __fdividef(2.0f, 1.0f + ea);
        }
        __syncthreads();   // all reads done before next iteration's stores

        // check-node update: exclusive products over this thread's 6 edges (registers only)
        float pre[6], suf[6];
        pre[0] = 1.0f;
#pragma unroll
        for (int j = 1; j < 6; ++j) pre[j] = pre[j - 1] * v2c[j - 1];
        suf[5] = 1.0f;
#pragma unroll
        for (int j = 4; j >= 0; --j) suf[j] = suf[j + 1] * v2c[j + 1];
#pragma unroll
        for (int j = 0; j < 6; ++j) {
            float y = 0.9995f * (pre[j] * suf[j]);
            // 2*atanh(y) = log((1+y)/(1-y));  |y| <= 0.9995 so 1-y >= 5e-4
            c2v[j] = __logf(__fdividef(1.0f + y, 1.0f - y));
        }
    }

    // publish final c2v, then each thread produces 2 variable outputs
#pragma unroll
    for (int j = 0; j < 6; ++j) sm[e0 + j] = c2v[j];
    __syncthreads();

    float* __restrict__ out_b = out + (size_t)b * NVAR;
#pragma unroll
    for (int k = 0; k < NVAR / MCHK; ++k) {
        const int v = c + k * MCHK;
        float marg = 0.0f;
#pragma unroll
        for (int p = 0; p < 3; ++p) {
            const int q = 3 * v + p;
            marg += sm[fin_idx[q]] * w_final[q];
        }
        marg += __ldg(&llr_b[v]) * llr_final[v];
        out_b[v] = __fdividef(1.0f, 1.0f + __expf(-marg));
    }
}

extern "C" void kernel_launch(void* const* d_in, const int* in_sizes, int n_in,
                              void* d_out, int out_size)
{
    // metadata order: llr, w_iter, llr_iter, w_final, llr_final,
    //                 v_sum_idx, seg_vsum, c_prod_idx, seg_cprod,
    //                 final_idx, seg_final, edge_var
    const float* llr       = (const float*)d_in[0];
    const float* w_iter    = (const float*)d_in[1];
    const float* llr_iter  = (const float*)d_in[2];
    const float* w_final   = (const float*)d_in[3];
    const float* llr_final = (const float*)d_in[4];
    const int*   vs_idx    = (const int*)  d_in[5];
    const int*   fin_idx   = (const int*)  d_in[9];
    const int*   edge_var  = (const int*)  d_in[11];
    float*       out       = (float*)d_out;

    const int B = in_sizes[0] / NVAR;   // batch size from llr element count

    bp_decode_kernel<<<B, MCHK>>>(llr, w_iter, llr_iter, w_final, llr_final,
                                  vs_idx, fin_idx, edge_var, out);
}

// round 2
// speedup vs baseline: 1.4491x; 1.4491x over previous
#include <cuda_runtime.h>

// Fixed problem structure (M=512 checks, N=1024 vars, SHIFTS=(0,7,101)):
//   E = 3072 edges, check degree 6, var degree 3.
//   edges sorted by (check,var) => check c owns edges [6c, 6c+6).
//   v_sum pairs: exactly 2 per edge, in edge order.
//   final pairs: exactly 3 per var, in var order.
#define ITERS 5
#define MCHK  512
#define NVAR  1024
#define NEDGE 3072

// Batch-invariant scratch, transposed to slot-major [j][c] for coalescing.
__device__ float2 g_w2  [ITERS * NEDGE];  // weight pair for edge (c,j)
__device__ float  g_lt  [ITERS * NEDGE];  // llr_iter[t][edge_var[e]] pre-gathered
__device__ int2   g_sib [NEDGE];          // sibling edge ids, TRANSLATED to j*512+c layout
__device__ int    g_ev  [NEDGE];          // variable of edge (c,j)
__device__ int    g_fidx[NEDGE];          // final-stage edge ids, translated
__device__ float  g_wf  [NEDGE];          // w_final, transposed

__global__ void prepack_kernel(const float* __restrict__ w_iter,
                               const float* __restrict__ llr_iter,
                               const int*   __restrict__ vs_idx,
                               const int*   __restrict__ edge_var,
                               const int*   __restrict__ fin_idx,
                               const float* __restrict__ w_final)
{
    const int c = threadIdx.x;   // 0..511
    const int t = blockIdx.x;    // 0..ITERS-1
#pragma unroll
    for (int j = 0; j < 6; ++j) {
        const int e = 6 * c + j;
        g_w2[t * NEDGE + j * MCHK + c] =
            make_float2(w_iter[t * 2 * NEDGE + 2 * e],
                        w_iter[t * 2 * NEDGE + 2 * e + 1]);
        g_lt[t * NEDGE + j * MCHK + c] = llr_iter[t * NVAR + edge_var[e]];
    }
    if (t == 0) {
#pragma unroll
        for (int j = 0; j < 6; ++j) {
            const int e  = 6 * c + j;
            const int s0 = vs_idx[2 * e];
            const int s1 = vs_idx[2 * e + 1];
            g_sib[j * MCHK + c] = make_int2((s0 % 6) * MCHK + s0 / 6,
                                            (s1 % 6) * MCHK + s1 / 6);
            g_ev[j * MCHK + c]  = edge_var[e];
        }
#pragma unroll
        for (int k = 0; k < 2; ++k)
#pragma unroll
            for (int p = 0; p < 3; ++p) {
                const int v = c + MCHK * k;
                const int q = 3 * v + p;
                const int e = fin_idx[q];
                g_fidx[(k * 3 + p) * MCHK + c] = (e % 6) * MCHK + e / 6;
                g_wf  [(k * 3 + p) * MCHK + c] = w_final[q];
            }
    }
}

__global__ __launch_bounds__(512, 2)
void bp_decode_kernel(const float* __restrict__ llr,        // [B, N]
                      const float* __restrict__ llr_final,  // [N]
                      float*       __restrict__ out)        // [B, N]
{
    __shared__ float sm[NEDGE];          // c2v message of edge (c,j) at [j*512+c]

    const int b = blockIdx.x;
    const int c = threadIdx.x;
    const float* __restrict__ llr_b = llr + (size_t)b * NVAR;

    // Prologue: graph constants (coalesced) + batch llr gather (near-coalesced,
    // circulant structure => ev[j] ~ c + const across the warp).
    int2  sib[6];
    float lv[6];
#pragma unroll
    for (int j = 0; j < 6; ++j) {
        sib[j] = g_sib[j * MCHK + c];
        lv[j]  = __ldg(&llr_b[g_ev[j * MCHK + c]]);
    }

    float c2v[6];
#pragma unroll
    for (int j = 0; j < 6; ++j) c2v[j] = 0.0f;

    for (int t = 0; t < ITERS; ++t) {
        // publish c2v messages (conflict-free STS: address = j*512 + c)
#pragma unroll
        for (int j = 0; j < 6; ++j) sm[j * MCHK + c] = c2v[j];
        __syncthreads();

        const float2* __restrict__ w2 = g_w2 + t * NEDGE;
        const float*  __restrict__ lt = g_lt + t * NEDGE;

        // variable-node update: v2c = tanh(0.5*(sum_sib c2v*w + llr*llr_iter))
        float v2c[6];
#pragma unroll
        for (int j = 0; j < 6; ++j) {
            const float2 w = w2[j * MCHK + c];                 // coalesced LDG.64
            const float summed = sm[sib[j].x] * w.x + sm[sib[j].y] * w.y;
            const float arg = summed + lv[j] * lt[j * MCHK + c]; // coalesced LDG.32
            // tanh(arg/2) = 1 - 2/(1+exp(arg)); NaN-safe at +-inf
            const float ea = __expf(arg);
            v2c[j] = 1.0f - __fdividef(2.0f, 1.0f + ea);
        }
        __syncthreads();   // all reads done before next iteration's stores

        // check-node update: exclusive products, register-only prefix/suffix
        float pre[6], suf[6];
        pre[0] = 1.0f;
#pragma unroll
        for (int j = 1; j < 6; ++j) pre[j] = pre[j - 1] * v2c[j - 1];
        suf[5] = 1.0f;
#pragma unroll
        for (int j = 4; j >= 0; --j) suf[j] = suf[j + 1] * v2c[j + 1];
#pragma unroll
        for (int j = 0; j < 6; ++j) {
            const float y = 0.9995f * (pre[j] * suf[j]);
            // 2*atanh(y) = log((1+y)/(1-y)); |y| <= 0.9995 so 1-y >= 5e-4
            c2v[j] = __logf(__fdividef(1.0f + y, 1.0f - y));
        }
    }

    // Epilogue: publish final c2v, then 2 variable outputs per thread.
#pragma unroll
    for (int j = 0; j < 6; ++j) sm[j * MCHK + c] = c2v[j];
    __syncthreads();

    float* __restrict__ out_b = out + (size_t)b * NVAR;
#pragma unroll
    for (int k = 0; k < 2; ++k) {
        const int v = c + MCHK * k;
        float marg = 0.0f;
#pragma unroll
        for (int p = 0; p < 3; ++p) {
            const int q = (k * 3 + p) * MCHK + c;              // coalesced
            marg += sm[g_fidx[q]] * g_wf[q];
        }
        marg += __ldg(&llr_b[v]) * llr_final[v];
        out_b[v] = __fdividef(1.0f, 1.0f + __expf(-marg));
    }
}

extern "C" void kernel_launch(void* const* d_in, const int* in_sizes, int n_in,
                              void* d_out, int out_size)
{
    // metadata order: llr, w_iter, llr_iter, w_final, llr_final,
    //                 v_sum_idx, seg_vsum, c_prod_idx, seg_cprod,
    //                 final_idx, seg_final, edge_var
    const float* llr       = (const float*)d_in[0];
    const float* w_iter    = (const float*)d_in[1];
    const float* llr_iter  = (const float*)d_in[2];
    const float* w_final   = (const float*)d_in[3];
    const float* llr_final = (const float*)d_in[4];
    const int*   vs_idx    = (const int*)  d_in[5];
    const int*   fin_idx   = (const int*)  d_in[9];
    const int*   edge_var  = (const int*)  d_in[11];
    float*       out       = (float*)d_out;

    const int B = in_sizes[0] / NVAR;

    prepack_kernel<<<ITERS, MCHK>>>(w_iter, llr_iter, vs_idx, edge_var,
                                    fin_idx, w_final);
    bp_decode_kernel<<<B, MCHK>>>(llr, llr_final, out);
}

// round 3
// speedup vs baseline: 1.4522x; 1.0022x over previous
#include <cuda_runtime.h>

// Fixed problem structure (M=512 checks, N=1024 vars, SHIFTS=(0,7,101)):
//   E = 3072 edges, check degree 6, var degree 3.
//   edges sorted by (check,var) => check c owns edges [6c, 6c+6).
#define ITERS 5
#define MCHK  512
#define NVAR  1024
#define NEDGE 3072

#define LOG2E 1.4426950408889634f
#define LN2   0.6931471805599453f

// Batch-invariant scratch, slot-major [j][c] for coalescing.
// Messages circulate in log2 units: c2v_l2 = c2v_true / ln2.
//   arg_for_EX2 = sum(w_iter * c2v_l2) + llr*(llr_iter*log2e)  [= arg_true*log2e]
//   => g_w2 = w_iter (ln2*log2e = 1), g_lt = llr_iter*log2e, g_wf = w_final*ln2.
__device__ float2 g_w2  [ITERS * NEDGE];
__device__ float  g_lt  [ITERS * NEDGE];
__device__ int2   g_sib [NEDGE];          // sibling edge ids, translated to j*512+c
__device__ int    g_ev  [NEDGE];
__device__ int    g_fidx[NEDGE];
__device__ float  g_wf  [NEDGE];

__global__ void prepack_kernel(const float* __restrict__ w_iter,
                               const float* __restrict__ llr_iter,
                               const int*   __restrict__ vs_idx,
                               const int*   __restrict__ edge_var,
                               const int*   __restrict__ fin_idx,
                               const float* __restrict__ w_final)
{
    const int c = threadIdx.x;
    const int t = blockIdx.x;
#pragma unroll
    for (int j = 0; j < 6; ++j) {
        const int e = 6 * c + j;
        g_w2[t * NEDGE + j * MCHK + c] =
            make_float2(w_iter[t * 2 * NEDGE + 2 * e],
                        w_iter[t * 2 * NEDGE + 2 * e + 1]);
        g_lt[t * NEDGE + j * MCHK + c] = llr_iter[t * NVAR + edge_var[e]] * LOG2E;
    }
    if (t == 0) {
#pragma unroll
        for (int j = 0; j < 6; ++j) {
            const int e  = 6 * c + j;
            const int s0 = vs_idx[2 * e];
            const int s1 = vs_idx[2 * e + 1];
            g_sib[j * MCHK + c] = make_int2((s0 % 6) * MCHK + s0 / 6,
                                            (s1 % 6) * MCHK + s1 / 6);
            g_ev[j * MCHK + c]  = edge_var[e];
        }
#pragma unroll
        for (int k = 0; k < 2; ++k)
#pragma unroll
            for (int p = 0; p < 3; ++p) {
                const int v = c + MCHK * k;
                const int q = 3 * v + p;
                const int e = fin_idx[q];
                g_fidx[(k * 3 + p) * MCHK + c] = (e % 6) * MCHK + e / 6;
                g_wf  [(k * 3 + p) * MCHK + c] = w_final[q] * LN2;
            }
    }
}

__global__ __launch_bounds__(512, 2)
void bp_decode_kernel(const float* __restrict__ llr,        // [B, N]
                      const float* __restrict__ llr_final,  // [N]
                      float*       __restrict__ out)        // [B, N]
{
    __shared__ float sm[2][NEDGE];      // double-buffered c2v (log2 units)

    const int b = blockIdx.x;
    const int c = threadIdx.x;
    const float* __restrict__ llr_b = llr + (size_t)b * NVAR;

    int2  sib[6];
    float lv[6];
#pragma unroll
    for (int j = 0; j < 6; ++j) {
        sib[j] = g_sib[j * MCHK + c];
        lv[j]  = __ldg(&llr_b[g_ev[j * MCHK + c]]);
    }

    float c2v[6];
#pragma unroll
    for (int j = 0; j < 6; ++j) c2v[j] = 0.0f;

    int cur = 0;
    for (int t = 0; t < ITERS; ++t) {
        // publish messages into the current buffer (conflict-free STS)
#pragma unroll
        for (int j = 0; j < 6; ++j) sm[cur][j * MCHK + c] = c2v[j];
        __syncthreads();
        // (single barrier: next iteration writes the OTHER buffer, so readers
        //  of this buffer are protected by the next iteration's barrier)

        const float2* __restrict__ w2 = g_w2 + t * NEDGE;
        const float*  __restrict__ lt = g_lt + t * NEDGE;

        // Variable update, rational form:
        //   v2c = tanh(arg_true/2) = (2^x - 1)/(2^x + 1),  x = arg_true*log2e
        float n[6], d[6];
#pragma unroll
        for (int j = 0; j < 6; ++j) {
            const float2 w = w2[j * MCHK + c];                   // coalesced LDG.64
            float x = sm[cur][sib[j].x] * w.x + sm[cur][sib[j].y] * w.y
                    + lv[j] * lt[j * MCHK + c];                  // coalesced LDG.32
            x = fminf(fmaxf(x, -25.0f), 25.0f);   // tanh==+-1.0f in f32 beyond this
            const float ea = exp2f(x);            // single MUFU (EX2)
            n[j] = ea - 1.0f;
            d[j] = ea + 1.0f;
        }

        // Check update: y_j = 0.9995 * prod_{k!=j} n_k/d_k kept as P/Q;
        //   c2v_l2 = log2((Q+P)/(Q-P)) = log2(Q+P) - log2(Q-P)   (2 MUFU, no RCP)
        float sn[6], sd[6];
        sn[5] = 1.0f; sd[5] = 1.0f;
#pragma unroll
        for (int j = 4; j >= 0; --j) {
            sn[j] = sn[j + 1] * n[j + 1];
            sd[j] = sd[j + 1] * d[j + 1];
        }
        float pn = 0.9995f, pd = 1.0f;
#pragma unroll
        for (int j = 0; j < 6; ++j) {
            const float P = pn * sn[j];
            const float Q = pd * sd[j];
            c2v[j] = __log2f(Q + P) - __log2f(Q - P);
            pn *= n[j];
            pd *= d[j];
        }
        cur ^= 1;
    }

    // Epilogue: publish final messages, 2 variable outputs per thread.
#pragma unroll
    for (int j = 0; j < 6; ++j) sm[cur][j * MCHK + c] = c2v[j];
    __syncthreads();

    float* __restrict__ out_b = out + (size_t)b * NVAR;
#pragma unroll
    for (int k = 0; k < 2; ++k) {
        const int v = c + MCHK * k;
        float marg = 0.0f;
#pragma unroll
        for (int p = 0; p < 3; ++p) {
            const int q = (k * 3 + p) * MCHK + c;                // coalesced
            marg += sm[cur][g_fidx[q]] * g_wf[q];                // wf prescaled *ln2
        }
        marg += __ldg(&llr_b[v]) * llr_final[v];
        out_b[v] = __fdividef(1.0f, 1.0f + __expf(-marg));
    }
}

extern "C" void kernel_launch(void* const* d_in, const int* in_sizes, int n_in,
                              void* d_out, int out_size)
{
    // metadata order: llr, w_iter, llr_iter, w_final, llr_final,
    //                 v_sum_idx, seg_vsum, c_prod_idx, seg_cprod,
    //                 final_idx, seg_final, edge_var
    const float* llr       = (const float*)d_in[0];
    const float* w_iter    = (const float*)d_in[1];
    const float* llr_iter  = (const float*)d_in[2];
    const float* w_final   = (const float*)d_in[3];
    const float* llr_final = (const float*)d_in[4];
    const int*   vs_idx    = (const int*)  d_in[5];
    const int*   fin_idx   = (const int*)  d_in[9];
    const int*   edge_var  = (const int*)  d_in[11];
    float*       out       = (float*)d_out;

    const int B = in_sizes[0] / NVAR;

    prepack_kernel<<<ITERS, MCHK>>>(w_iter, llr_iter, vs_idx, edge_var,
                                    fin_idx, w_final);
    bp_decode_kernel<<<B, MCHK>>>(llr, llr_final, out);
}